// round 13
// baseline (speedup 1.0000x reference)
#include <cuda_runtime.h>
#include <math.h>

#define NB   4
#define NH   16
#define LSEQ 2048
#define NDH  64
#define ND   1024
#define NBH  64
#define TOPK 205
#define PSTR 2052   // sP row stride (floats)

// scratch (static device memory; allocation APIs forbidden)
__device__ float g_q[8388608];        // [bh][2048][64]
__device__ float g_kT[8388608];       // [bh][64][2048]
__device__ float g_v[8388608];        // [bh][2048][64]
__device__ float g_ctx[8388608];      // [B*Lq][1024]

typedef unsigned long long ull;
__device__ __forceinline__ ull pk2(float lo, float hi) {
    ull r; asm("mov.b64 %0, {%1, %2};" : "=l"(r) : "f"(lo), "f"(hi)); return r;
}
__device__ __forceinline__ void upk2(ull v, float &lo, float &hi) {
    asm("mov.b64 {%0, %1}, %2;" : "=f"(lo), "=f"(hi) : "l"(v));
}
__device__ __forceinline__ void fma2(ull &d, ull a, ull b) {
    asm("fma.rn.f32x2 %0, %1, %2, %3;" : "=l"(d) : "l"(a), "l"(b), "l"(d));
}
// fast tanh: 1 - 2/(1+e^{2x}); __expf err ~2^-21, saturates correctly at +-inf
__device__ __forceinline__ float fast_tanh(float x) {
    const float e = __expf(2.0f * x);
    return 1.0f - __fdividef(2.0f, 1.0f + e);
}

// ---------------------------------------------------------------------------
// Double-buffered NT GEMM tile: C[128,128] = A@W^T + bias. BK=16, 256 thr.
// 4+4 split micro-tile (conflict-free B reads, broadcast A reads), XOR-swizzled
// staging stores. mode: 0 plain / 1 split-head / 2 +tanh / 3 split-head-T.
// ---------------------------------------------------------------------------
__device__ __forceinline__ void gemm_dbuf(
    const float* __restrict__ A, const float* __restrict__ W,
    const float* __restrict__ bias, float* __restrict__ outp,
    int N, int K, int mode, int Lseq, int m0, int n0,
    float As[2][16][132], float Bs[2][16][132])
{
    const int tid  = threadIdx.x;
    const int ty   = tid >> 4;
    const int tx   = tid & 15;
    const int lrow = tid >> 1;
    const int lc   = (tid & 1) * 8;
    const int lsw  = lrow ^ (lc << 1);   // lc=8 -> ^16 ; lc=0 -> ^0

    const float* Ap = A + (size_t)(m0 + lrow) * K + lc;
    const float* Wp = W + (size_t)(n0 + lrow) * K + lc;

    ull acc[8][4];
#pragma unroll
    for (int i = 0; i < 8; i++)
#pragma unroll
        for (int j = 0; j < 4; j++) acc[i][j] = 0ull;

    const int nch = K >> 4;
    float4 a0 = *(const float4*)(Ap);
    float4 a1 = *(const float4*)(Ap + 4);
    float4 w0 = *(const float4*)(Wp);
    float4 w1 = *(const float4*)(Wp + 4);

    As[0][lc+0][lsw]=a0.x; As[0][lc+1][lsw]=a0.y; As[0][lc+2][lsw]=a0.z; As[0][lc+3][lsw]=a0.w;
    As[0][lc+4][lsw]=a1.x; As[0][lc+5][lsw]=a1.y; As[0][lc+6][lsw]=a1.z; As[0][lc+7][lsw]=a1.w;
    Bs[0][lc+0][lsw]=w0.x; Bs[0][lc+1][lsw]=w0.y; Bs[0][lc+2][lsw]=w0.z; Bs[0][lc+3][lsw]=w0.w;
    Bs[0][lc+4][lsw]=w1.x; Bs[0][lc+5][lsw]=w1.y; Bs[0][lc+6][lsw]=w1.z; Bs[0][lc+7][lsw]=w1.w;
    if (nch > 1) {
        a0 = *(const float4*)(Ap + 16); a1 = *(const float4*)(Ap + 20);
        w0 = *(const float4*)(Wp + 16); w1 = *(const float4*)(Wp + 20);
    }
    __syncthreads();

    for (int c = 0; c < nch; c++) {
        const int cur = c & 1;
        if (c + 1 < nch) {
            const int nb = cur ^ 1;
            As[nb][lc+0][lsw]=a0.x; As[nb][lc+1][lsw]=a0.y; As[nb][lc+2][lsw]=a0.z; As[nb][lc+3][lsw]=a0.w;
            As[nb][lc+4][lsw]=a1.x; As[nb][lc+5][lsw]=a1.y; As[nb][lc+6][lsw]=a1.z; As[nb][lc+7][lsw]=a1.w;
            Bs[nb][lc+0][lsw]=w0.x; Bs[nb][lc+1][lsw]=w0.y; Bs[nb][lc+2][lsw]=w0.z; Bs[nb][lc+3][lsw]=w0.w;
            Bs[nb][lc+4][lsw]=w1.x; Bs[nb][lc+5][lsw]=w1.y; Bs[nb][lc+6][lsw]=w1.z; Bs[nb][lc+7][lsw]=w1.w;
            if (c + 2 < nch) {
                const float* ap = Ap + (c + 2) * 16;
                const float* wp = Wp + (c + 2) * 16;
                a0 = *(const float4*)ap;  a1 = *(const float4*)(ap + 4);
                w0 = *(const float4*)wp;  w1 = *(const float4*)(wp + 4);
            }
        }
#pragma unroll
        for (int kk = 0; kk < 16; kk++) {
            const int sw = (kk >= 8) ? 16 : 0;      // compile-time per unrolled kk
            const float4 af0 = *(const float4*)&As[cur][kk][(ty * 4) ^ sw];
            const float4 af1 = *(const float4*)&As[cur][kk][(64 + ty * 4) ^ sw];
            const float4 bf0 = *(const float4*)&Bs[cur][kk][(tx * 4) ^ sw];
            const float4 bf1 = *(const float4*)&Bs[cur][kk][(64 + tx * 4) ^ sw];
            const ull bp0 = pk2(bf0.x, bf0.y);
            const ull bp1 = pk2(bf0.z, bf0.w);
            const ull bp2 = pk2(bf1.x, bf1.y);
            const ull bp3 = pk2(bf1.z, bf1.w);
            const float av[8] = {af0.x, af0.y, af0.z, af0.w, af1.x, af1.y, af1.z, af1.w};
#pragma unroll
            for (int i = 0; i < 8; i++) {
                const ull ad = pk2(av[i], av[i]);
                fma2(acc[i][0], ad, bp0);
                fma2(acc[i][1], ad, bp1);
                fma2(acc[i][2], ad, bp2);
                fma2(acc[i][3], ad, bp3);
            }
        }
        __syncthreads();
    }

#pragma unroll
    for (int i = 0; i < 8; i++) {
        const int m = m0 + ((i < 4) ? (ty * 4 + i) : (64 + ty * 4 + i - 4));
#pragma unroll
        for (int j = 0; j < 4; j++) {
            float c0, c1;
            upk2(acc[i][j], c0, c1);
            const int n = n0 + ((j < 2) ? (tx * 4 + j * 2) : (64 + tx * 4 + (j - 2) * 2));
            c0 += bias[n];
            c1 += bias[n + 1];
            if (mode == 0) {
                outp[(size_t)m * N + n]     = c0;
                outp[(size_t)m * N + n + 1] = c1;
            } else if (mode == 3) {
                const int b = m / Lseq, l = m - b * Lseq;
                const int h = n >> 6, dh = n & 63;
                const size_t o = ((size_t)(b * NH + h) * NDH + dh) * Lseq + l;
                outp[o]        = c0;
                outp[o + Lseq] = c1;
            } else {
                if (mode == 2) { c0 = fast_tanh(c0); c1 = fast_tanh(c1); }
                const int b = m / Lseq, l = m - b * Lseq;
                const int h = n >> 6, dh = n & 63;
                const size_t o = (((size_t)(b * NH + h)) * Lseq + l) * NDH + dh;
                outp[o]     = c0;
                outp[o + 1] = c1;
            }
        }
    }
}

__global__ void __launch_bounds__(256, 2)
proj_qkv(const float* __restrict__ q_in, const float* __restrict__ k_in,
         const float* __restrict__ Wq, const float* __restrict__ bq,
         const float* __restrict__ Wk, const float* __restrict__ bk,
         const float* __restrict__ Wv, const float* __restrict__ bv,
         float* pq, float* pkT, float* pv)
{
    __shared__ float As[2][16][132];
    __shared__ float Bs[2][16][132];
    const int z = blockIdx.z;
    const float* A    = (z == 0) ? q_in : k_in;
    const float* W    = (z == 0) ? Wq : (z == 1) ? Wk : Wv;
    const float* bias = (z == 0) ? bq : (z == 1) ? bk : bv;
    float* outp       = (z == 0) ? pq : (z == 1) ? pkT : pv;
    const int mode    = (z == 0) ? 1 : (z == 1) ? 3 : 2;
    gemm_dbuf(A, W, bias, outp, ND, ND, mode, LSEQ,
              blockIdx.y * 128, blockIdx.x * 128, As, Bs);
}

__global__ void __launch_bounds__(256, 2)
out_proj(const float* __restrict__ A, const float* __restrict__ W,
         const float* __restrict__ bias, float* __restrict__ outp)
{
    __shared__ float As[2][16][132];
    __shared__ float Bs[2][16][132];
    gemm_dbuf(A, W, bias, outp, ND, ND, 0, LSEQ,
              blockIdx.y * 128, blockIdx.x * 128, As, Bs);
}

// ---------------------------------------------------------------------------
// Fused attention: CTA = (bh, 16 q-rows), 512 threads, ~148 KB smem.
// logits -> softmax(e, __expf) -> exact top-k on e (pass-0 histogram fused
// into the exp sweep; inv folded into final write) -> ctx = attn@v * q.
// ---------------------------------------------------------------------------
__global__ void __launch_bounds__(512, 1)
fused_attn(const int* __restrict__ mask)
{
    extern __shared__ float sm[];
    float* sP  = sm;                                      // [16][PSTR]
    float* sQT = sm + 16 * PSTR;                          // [64][16]
    unsigned* hist = (unsigned*)(sm + 16 * PSTR + 1024);  // [16][256]

    const int tid = threadIdx.x;
    const int bh  = blockIdx.y;
    const int m0  = blockIdx.x * 16;
    const int b   = bh >> 4, h = bh & 15;

    // ---- phase 0: q tile, transposed into smem ----
    for (int i = tid; i < 1024; i += 512) {
        const int r = i >> 6, d = i & 63;
        sQT[d * 16 + r] = g_q[((size_t)bh * LSEQ + m0 + r) * NDH + d];
    }
    __syncthreads();

    // ---- phase 1: logits for cols [tid*4, tid*4+4), all 16 rows ----
    {
        const int n0 = tid * 4;
        const float* kb = g_kT + (size_t)bh * NDH * LSEQ + n0;
        ull acc[8][4];
#pragma unroll
        for (int i = 0; i < 8; i++)
#pragma unroll
            for (int j = 0; j < 4; j++) acc[i][j] = 0ull;

#define PROC1(KV, D) do {                                                   \
        const ull k0 = pk2((KV).x, (KV).x);                                 \
        const ull k1 = pk2((KV).y, (KV).y);                                 \
        const ull k2 = pk2((KV).z, (KV).z);                                 \
        const ull k3 = pk2((KV).w, (KV).w);                                 \
        const ull* qrow = (const ull*)&sQT[(D) * 16];                       \
        _Pragma("unroll")                                                   \
        for (int rp = 0; rp < 8; rp++) {                                    \
            const ull qq = qrow[rp];                                        \
            fma2(acc[rp][0], qq, k0);                                       \
            fma2(acc[rp][1], qq, k1);                                       \
            fma2(acc[rp][2], qq, k2);                                       \
            fma2(acc[rp][3], qq, k3);                                       \
        } } while (0)

        float4 c0 = *(const float4*)(kb);
        float4 c1 = *(const float4*)(kb + LSEQ);
        for (int d0 = 0; d0 < 62; d0 += 2) {
            const float4 nx0 = *(const float4*)(kb + (size_t)(d0 + 2) * LSEQ);
            const float4 nx1 = *(const float4*)(kb + (size_t)(d0 + 3) * LSEQ);
            PROC1(c0, d0);
            PROC1(c1, d0 + 1);
            c0 = nx0; c1 = nx1;
        }
        PROC1(c0, 62);
        PROC1(c1, 63);
#undef PROC1

        const int4 mv = *(const int4*)(mask + b * LSEQ + n0);
        const int mk[4] = {mv.x, mv.y, mv.z, mv.w};
#pragma unroll
        for (int rp = 0; rp < 8; rp++) {
            float lo[4], hi[4];
#pragma unroll
            for (int c = 0; c < 4; c++) {
                upk2(acc[rp][c], lo[c], hi[c]);
                lo[c] = mk[c] ? -20000.0f : lo[c] * 0.25f;   // SCALE*2 folded
                hi[c] = mk[c] ? -20000.0f : hi[c] * 0.25f;
            }
            *(float4*)&sP[(2 * rp)     * PSTR + n0] = make_float4(lo[0], lo[1], lo[2], lo[3]);
            *(float4*)&sP[(2 * rp + 1) * PSTR + n0] = make_float4(hi[0], hi[1], hi[2], hi[3]);
        }
    }
    __syncthreads();

    // ---- phase 2: exp(+hist pass 0) + exact top-k on e; inv folded ----
    {
        const int w = tid >> 5, l = tid & 31;
        float* pr = sP + w * PSTR;
        unsigned* hw = hist + w * 256;

        for (int bi = l; bi < 256; bi += 32) hw[bi] = 0u;   // zero pass-0 hist

        float mx = -3.0e38f;
        for (int i = l; i < LSEQ; i += 32) mx = fmaxf(mx, pr[i]);
#pragma unroll
        for (int o = 16; o; o >>= 1) mx = fmaxf(mx, __shfl_xor_sync(0xffffffffu, mx, o));
        __syncwarp();

        // exp sweep: write e, accumulate sum, and build pass-0 histogram
        float s = 0.0f;
        for (int i = l; i < LSEQ; i += 32) {
            const float e = __expf(pr[i] - mx);
            pr[i] = e;
            s += e;
            atomicAdd(&hw[__float_as_uint(e) >> 24], 1u);
        }
#pragma unroll
        for (int o = 16; o; o >>= 1) s += __shfl_xor_sync(0xffffffffu, s, o);
        const float inv = 1.0f / s;
        __syncwarp();

        unsigned pref = 0; int need = TOPK;
        const unsigned pmasks[4] = {0u, 0xFF000000u, 0xFFFF0000u, 0xFFFFFF00u};
#pragma unroll
        for (int pass = 0; pass < 4; pass++) {
            const int shift = 24 - pass * 8;
            if (pass > 0) {
                const unsigned pmask = pmasks[pass];
                for (int bi = l; bi < 256; bi += 32) hw[bi] = 0u;
                __syncwarp();
                for (int i = l; i < LSEQ; i += 32) {
                    const unsigned u = __float_as_uint(pr[i]);
                    if ((u & pmask) == pref) atomicAdd(&hw[(u >> shift) & 255], 1u);
                }
                __syncwarp();
            }
            if (l == 0) {
                unsigned cum = 0; int d = 255;
                for (; d > 0; d--) {
                    const unsigned cc = hw[d];
                    if (cum + cc >= (unsigned)need) break;
                    cum += cc;
                }
                pref |= (unsigned)d << shift;
                need -= (int)cum;
            }
            pref = __shfl_sync(0xffffffffu, pref, 0);
            need = __shfl_sync(0xffffffffu, need, 0);
            __syncwarp();
        }
        const float thr = __uint_as_float(pref);
        for (int i = l; i < LSEQ; i += 32) {
            const float v = pr[i];
            pr[i] = (v >= thr) ? v * inv : 0.0f;
        }
    }
    __syncthreads();

    // ---- phase 3: ctx = P @ v, gate by q.  Thread s handles n in
    //      {2s, 2s+1, 2s+64, 2s+65, ...} so P loads are broadcast LDS.64. ----
    {
        const int g = tid & 15;          // dh slice g*4..+3
        const int s = tid >> 4;          // pair slot (0..31)
        const float* vb = g_v + (size_t)bh * LSEQ * NDH + g * 4;
        ull acc[16][2];
#pragma unroll
        for (int r = 0; r < 16; r++) { acc[r][0] = 0ull; acc[r][1] = 0ull; }

#define PROC3(V0, V1, N) do {                                               \
        const ull va01 = pk2((V0).x, (V0).y);                               \
        const ull va23 = pk2((V0).z, (V0).w);                               \
        const ull vb01 = pk2((V1).x, (V1).y);                               \
        const ull vb23 = pk2((V1).z, (V1).w);                               \
        _Pragma("unroll")                                                   \
        for (int r = 0; r < 16; r++) {                                      \
            const ull ppair = *(const ull*)&sP[r * PSTR + (N)];             \
            float p0, p1; upk2(ppair, p0, p1);                              \
            const ull pa = pk2(p0, p0);                                     \
            const ull pb = pk2(p1, p1);                                     \
            fma2(acc[r][0], pa, va01);                                      \
            fma2(acc[r][1], pa, va23);                                      \
            fma2(acc[r][0], pb, vb01);                                      \
            fma2(acc[r][1], pb, vb23);                                      \
        } } while (0)

        float4 v0 = *(const float4*)(vb + (size_t)(2 * s)     * NDH);
        float4 v1 = *(const float4*)(vb + (size_t)(2 * s + 1) * NDH);
        int n = 2 * s;
        for (; n + 64 < LSEQ; n += 64) {
            const float4 w0 = *(const float4*)(vb + (size_t)(n + 64) * NDH);
            const float4 w1 = *(const float4*)(vb + (size_t)(n + 65) * NDH);
            PROC3(v0, v1, n);
            v0 = w0; v1 = w1;
        }
        PROC3(v0, v1, n);
#undef PROC3
        __syncthreads();                  // all reads of sP done

        float* sR = sm;                   // overlay partials on sP: [32][16][64]
#pragma unroll
        for (int r = 0; r < 16; r++) {
            float a0, a1, a2, a3;
            upk2(acc[r][0], a0, a1);
            upk2(acc[r][1], a2, a3);
            *(float4*)&sR[((s * 16 + r) << 6) + (g << 2)] = make_float4(a0, a1, a2, a3);
        }
        __syncthreads();

        for (int o = tid; o < 1024; o += 512) {
            float c = 0.0f;
#pragma unroll
            for (int s2 = 0; s2 < 32; s2++) c += sR[(s2 << 10) + o];
            const int r = o >> 6, dh = o & 63;
            c *= sQT[dh * 16 + r];
            g_ctx[((size_t)(b * LSEQ) + m0 + r) * ND + h * NDH + dh] = c;
        }
    }
}

// ---------------------------------------------------------------------------
extern "C" void kernel_launch(void* const* d_in, const int* in_sizes, int n_in,
                              void* d_out, int out_size)
{
    const float* q_in = (const float*)d_in[0];
    const float* k_in = (const float*)d_in[1];
    const float* Wq   = (const float*)d_in[2];
    const float* bq   = (const float*)d_in[3];
    const float* Wk   = (const float*)d_in[4];
    const float* bk   = (const float*)d_in[5];
    const float* Wv   = (const float*)d_in[6];
    const float* bv   = (const float*)d_in[7];
    const float* Wo   = (const float*)d_in[8];
    const float* bo   = (const float*)d_in[9];
    const int*   mask = (const int*)d_in[10];
    float* out = (float*)d_out;

    void *pq = 0, *pk = 0, *pv = 0, *pctx = 0;
    cudaGetSymbolAddress(&pq, g_q);
    cudaGetSymbolAddress(&pk, g_kT);
    cudaGetSymbolAddress(&pv, g_v);
    cudaGetSymbolAddress(&pctx, g_ctx);

    const int smemb = (16 * PSTR + 1024 + 16 * 256) * 4;   // 151808 B
    cudaFuncSetAttribute(fused_attn, cudaFuncAttributeMaxDynamicSharedMemorySize, smemb);

    const dim3 thr(256);

    proj_qkv<<<dim3(ND / 128, (NB * LSEQ) / 128, 3), thr>>>(
        q_in, k_in, Wq, bq, Wk, bk, Wv, bv,
        (float*)pq, (float*)pk, (float*)pv);

    fused_attn<<<dim3(LSEQ / 16, NBH), 512, smemb>>>(mask);

    out_proj<<<dim3(ND / 128, (NB * LSEQ) / 128), thr>>>(
        (const float*)pctx, Wo, bo, out);
}

// round 16
// speedup vs baseline: 1.4095x; 1.4095x over previous
#include <cuda_runtime.h>
#include <math.h>

#define NB   4
#define NH   16
#define LSEQ 2048
#define NDH  64
#define ND   1024
#define NBH  64
#define TOPK 205
#define PSTR 2052   // sP row stride (floats)

// scratch (static device memory; allocation APIs forbidden)
__device__ float g_q[8388608];        // [bh][2048][64]
__device__ float g_kT[8388608];       // [bh][64][2048]
__device__ float g_v[8388608];        // [bh][2048][64]
__device__ float g_ctx[8388608];      // [B*Lq][1024]

typedef unsigned long long ull;
__device__ __forceinline__ ull pk2(float lo, float hi) {
    ull r; asm("mov.b64 %0, {%1, %2};" : "=l"(r) : "f"(lo), "f"(hi)); return r;
}
__device__ __forceinline__ void upk2(ull v, float &lo, float &hi) {
    asm("mov.b64 {%0, %1}, %2;" : "=f"(lo), "=f"(hi) : "l"(v));
}
__device__ __forceinline__ void fma2(ull &d, ull a, ull b) {
    asm("fma.rn.f32x2 %0, %1, %2, %3;" : "=l"(d) : "l"(a), "l"(b), "l"(d));
}

// ---------------------------------------------------------------------------
// Double-buffered NT GEMM tile: C[128,128] = A@W^T + bias. BK=16, 256 thr.
// 4+4 split micro-tile (conflict-free B reads, broadcast A reads), XOR-swizzled
// staging stores. mode: 0 plain / 1 split-head / 2 +tanh / 3 split-head-T.
// ---------------------------------------------------------------------------
__device__ __forceinline__ void gemm_dbuf(
    const float* __restrict__ A, const float* __restrict__ W,
    const float* __restrict__ bias, float* __restrict__ outp,
    int N, int K, int mode, int Lseq, int m0, int n0,
    float As[2][16][132], float Bs[2][16][132])
{
    const int tid  = threadIdx.x;
    const int ty   = tid >> 4;
    const int tx   = tid & 15;
    const int lrow = tid >> 1;
    const int lc   = (tid & 1) * 8;
    const int lsw  = lrow ^ (lc << 1);   // lc=8 -> ^16 ; lc=0 -> ^0

    const float* Ap = A + (size_t)(m0 + lrow) * K + lc;
    const float* Wp = W + (size_t)(n0 + lrow) * K + lc;

    ull acc[8][4];
#pragma unroll
    for (int i = 0; i < 8; i++)
#pragma unroll
        for (int j = 0; j < 4; j++) acc[i][j] = 0ull;

    const int nch = K >> 4;
    float4 a0 = *(const float4*)(Ap);
    float4 a1 = *(const float4*)(Ap + 4);
    float4 w0 = *(const float4*)(Wp);
    float4 w1 = *(const float4*)(Wp + 4);

    As[0][lc+0][lsw]=a0.x; As[0][lc+1][lsw]=a0.y; As[0][lc+2][lsw]=a0.z; As[0][lc+3][lsw]=a0.w;
    As[0][lc+4][lsw]=a1.x; As[0][lc+5][lsw]=a1.y; As[0][lc+6][lsw]=a1.z; As[0][lc+7][lsw]=a1.w;
    Bs[0][lc+0][lsw]=w0.x; Bs[0][lc+1][lsw]=w0.y; Bs[0][lc+2][lsw]=w0.z; Bs[0][lc+3][lsw]=w0.w;
    Bs[0][lc+4][lsw]=w1.x; Bs[0][lc+5][lsw]=w1.y; Bs[0][lc+6][lsw]=w1.z; Bs[0][lc+7][lsw]=w1.w;
    if (nch > 1) {
        a0 = *(const float4*)(Ap + 16); a1 = *(const float4*)(Ap + 20);
        w0 = *(const float4*)(Wp + 16); w1 = *(const float4*)(Wp + 20);
    }
    __syncthreads();

    for (int c = 0; c < nch; c++) {
        const int cur = c & 1;
        if (c + 1 < nch) {
            const int nb = cur ^ 1;
            As[nb][lc+0][lsw]=a0.x; As[nb][lc+1][lsw]=a0.y; As[nb][lc+2][lsw]=a0.z; As[nb][lc+3][lsw]=a0.w;
            As[nb][lc+4][lsw]=a1.x; As[nb][lc+5][lsw]=a1.y; As[nb][lc+6][lsw]=a1.z; As[nb][lc+7][lsw]=a1.w;
            Bs[nb][lc+0][lsw]=w0.x; Bs[nb][lc+1][lsw]=w0.y; Bs[nb][lc+2][lsw]=w0.z; Bs[nb][lc+3][lsw]=w0.w;
            Bs[nb][lc+4][lsw]=w1.x; Bs[nb][lc+5][lsw]=w1.y; Bs[nb][lc+6][lsw]=w1.z; Bs[nb][lc+7][lsw]=w1.w;
            if (c + 2 < nch) {
                const float* ap = Ap + (c + 2) * 16;
                const float* wp = Wp + (c + 2) * 16;
                a0 = *(const float4*)ap;  a1 = *(const float4*)(ap + 4);
                w0 = *(const float4*)wp;  w1 = *(const float4*)(wp + 4);
            }
        }
#pragma unroll
        for (int kk = 0; kk < 16; kk++) {
            const int sw = (kk >= 8) ? 16 : 0;      // compile-time per unrolled kk
            const float4 af0 = *(const float4*)&As[cur][kk][(ty * 4) ^ sw];
            const float4 af1 = *(const float4*)&As[cur][kk][(64 + ty * 4) ^ sw];
            const float4 bf0 = *(const float4*)&Bs[cur][kk][(tx * 4) ^ sw];
            const float4 bf1 = *(const float4*)&Bs[cur][kk][(64 + tx * 4) ^ sw];
            const ull bp0 = pk2(bf0.x, bf0.y);
            const ull bp1 = pk2(bf0.z, bf0.w);
            const ull bp2 = pk2(bf1.x, bf1.y);
            const ull bp3 = pk2(bf1.z, bf1.w);
            const float av[8] = {af0.x, af0.y, af0.z, af0.w, af1.x, af1.y, af1.z, af1.w};
#pragma unroll
            for (int i = 0; i < 8; i++) {
                const ull ad = pk2(av[i], av[i]);
                fma2(acc[i][0], ad, bp0);
                fma2(acc[i][1], ad, bp1);
                fma2(acc[i][2], ad, bp2);
                fma2(acc[i][3], ad, bp3);
            }
        }
        __syncthreads();
    }

#pragma unroll
    for (int i = 0; i < 8; i++) {
        const int m = m0 + ((i < 4) ? (ty * 4 + i) : (64 + ty * 4 + i - 4));
#pragma unroll
        for (int j = 0; j < 4; j++) {
            float c0, c1;
            upk2(acc[i][j], c0, c1);
            const int n = n0 + ((j < 2) ? (tx * 4 + j * 2) : (64 + tx * 4 + (j - 2) * 2));
            c0 += bias[n];
            c1 += bias[n + 1];
            if (mode == 0) {
                outp[(size_t)m * N + n]     = c0;
                outp[(size_t)m * N + n + 1] = c1;
            } else if (mode == 3) {
                const int b = m / Lseq, l = m - b * Lseq;
                const int h = n >> 6, dh = n & 63;
                const size_t o = ((size_t)(b * NH + h) * NDH + dh) * Lseq + l;
                outp[o]        = c0;
                outp[o + Lseq] = c1;
            } else {
                if (mode == 2) { c0 = tanhf(c0); c1 = tanhf(c1); }
                const int b = m / Lseq, l = m - b * Lseq;
                const int h = n >> 6, dh = n & 63;
                const size_t o = (((size_t)(b * NH + h)) * Lseq + l) * NDH + dh;
                outp[o]     = c0;
                outp[o + 1] = c1;
            }
        }
    }
}

__global__ void __launch_bounds__(256, 2)
proj_qkv(const float* __restrict__ q_in, const float* __restrict__ k_in,
         const float* __restrict__ Wq, const float* __restrict__ bq,
         const float* __restrict__ Wk, const float* __restrict__ bk,
         const float* __restrict__ Wv, const float* __restrict__ bv,
         float* pq, float* pkT, float* pv)
{
    __shared__ float As[2][16][132];
    __shared__ float Bs[2][16][132];
    const int z = blockIdx.z;
    const float* A    = (z == 0) ? q_in : k_in;
    const float* W    = (z == 0) ? Wq : (z == 1) ? Wk : Wv;
    const float* bias = (z == 0) ? bq : (z == 1) ? bk : bv;
    float* outp       = (z == 0) ? pq : (z == 1) ? pkT : pv;
    const int mode    = (z == 0) ? 1 : (z == 1) ? 3 : 2;
    gemm_dbuf(A, W, bias, outp, ND, ND, mode, LSEQ,
              blockIdx.y * 128, blockIdx.x * 128, As, Bs);
}

__global__ void __launch_bounds__(256, 2)
out_proj(const float* __restrict__ A, const float* __restrict__ W,
         const float* __restrict__ bias, float* __restrict__ outp)
{
    __shared__ float As[2][16][132];
    __shared__ float Bs[2][16][132];
    gemm_dbuf(A, W, bias, outp, ND, ND, 0, LSEQ,
              blockIdx.y * 128, blockIdx.x * 128, As, Bs);
}

// ---------------------------------------------------------------------------
// Fused attention: CTA = (bh, 16 q-rows), 512 threads, ~148 KB smem.
// logits -> softmax(e, __expf) -> exact top-k on e (warp-parallel bucket
// selection; inv folded into final write) -> ctx = attn@v * q.
// ---------------------------------------------------------------------------
__global__ void __launch_bounds__(512, 1)
fused_attn(const int* __restrict__ mask)
{
    extern __shared__ float sm[];
    float* sP  = sm;                                      // [16][PSTR]
    float* sQT = sm + 16 * PSTR;                          // [64][16]
    unsigned* hist = (unsigned*)(sm + 16 * PSTR + 1024);  // [16][256]

    const int tid = threadIdx.x;
    const int bh  = blockIdx.y;
    const int m0  = blockIdx.x * 16;
    const int b   = bh >> 4, h = bh & 15;

    // ---- phase 0: q tile, transposed into smem ----
    for (int i = tid; i < 1024; i += 512) {
        const int r = i >> 6, d = i & 63;
        sQT[d * 16 + r] = g_q[((size_t)bh * LSEQ + m0 + r) * NDH + d];
    }
    __syncthreads();

    // ---- phase 1: logits for cols [tid*4, tid*4+4), all 16 rows ----
    {
        const int n0 = tid * 4;
        const float* kb = g_kT + (size_t)bh * NDH * LSEQ + n0;
        ull acc[8][4];
#pragma unroll
        for (int i = 0; i < 8; i++)
#pragma unroll
            for (int j = 0; j < 4; j++) acc[i][j] = 0ull;

#define PROC1(KV, D) do {                                                   \
        const ull k0 = pk2((KV).x, (KV).x);                                 \
        const ull k1 = pk2((KV).y, (KV).y);                                 \
        const ull k2 = pk2((KV).z, (KV).z);                                 \
        const ull k3 = pk2((KV).w, (KV).w);                                 \
        const ull* qrow = (const ull*)&sQT[(D) * 16];                       \
        _Pragma("unroll")                                                   \
        for (int rp = 0; rp < 8; rp++) {                                    \
            const ull qq = qrow[rp];                                        \
            fma2(acc[rp][0], qq, k0);                                       \
            fma2(acc[rp][1], qq, k1);                                       \
            fma2(acc[rp][2], qq, k2);                                       \
            fma2(acc[rp][3], qq, k3);                                       \
        } } while (0)

        float4 c0 = *(const float4*)(kb);
        float4 c1 = *(const float4*)(kb + LSEQ);
        for (int d0 = 0; d0 < 62; d0 += 2) {
            const float4 nx0 = *(const float4*)(kb + (size_t)(d0 + 2) * LSEQ);
            const float4 nx1 = *(const float4*)(kb + (size_t)(d0 + 3) * LSEQ);
            PROC1(c0, d0);
            PROC1(c1, d0 + 1);
            c0 = nx0; c1 = nx1;
        }
        PROC1(c0, 62);
        PROC1(c1, 63);
#undef PROC1

        const int4 mv = *(const int4*)(mask + b * LSEQ + n0);
        const int mk[4] = {mv.x, mv.y, mv.z, mv.w};
#pragma unroll
        for (int rp = 0; rp < 8; rp++) {
            float lo[4], hi[4];
#pragma unroll
            for (int c = 0; c < 4; c++) {
                upk2(acc[rp][c], lo[c], hi[c]);
                lo[c] = mk[c] ? -20000.0f : lo[c] * 0.25f;   // SCALE*2 folded
                hi[c] = mk[c] ? -20000.0f : hi[c] * 0.25f;
            }
            *(float4*)&sP[(2 * rp)     * PSTR + n0] = make_float4(lo[0], lo[1], lo[2], lo[3]);
            *(float4*)&sP[(2 * rp + 1) * PSTR + n0] = make_float4(hi[0], hi[1], hi[2], hi[3]);
        }
    }
    __syncthreads();

    // ---- phase 2: exp + exact top-k on e (one warp per row); inv folded.
    //      Bucket selection is warp-parallel (suffix scan + ballot), not a
    //      serial lane-0 walk. ----
    {
        const int w = tid >> 5, l = tid & 31;
        float* pr = sP + w * PSTR;
        unsigned* hw = hist + w * 256;

        float mx = -3.0e38f;
        for (int i = l; i < LSEQ; i += 32) mx = fmaxf(mx, pr[i]);
#pragma unroll
        for (int o = 16; o; o >>= 1) mx = fmaxf(mx, __shfl_xor_sync(0xffffffffu, mx, o));

        float s = 0.0f;
        for (int i = l; i < LSEQ; i += 32) { const float e = __expf(pr[i] - mx); pr[i] = e; s += e; }
#pragma unroll
        for (int o = 16; o; o >>= 1) s += __shfl_xor_sync(0xffffffffu, s, o);
        const float inv = 1.0f / s;
        __syncwarp();

        unsigned pref = 0; int need = TOPK;
        const unsigned pmasks[4] = {0u, 0xFF000000u, 0xFFFF0000u, 0xFFFFFF00u};
#pragma unroll
        for (int pass = 0; pass < 4; pass++) {
            const int shift = 24 - pass * 8;
            const unsigned pmask = pmasks[pass];
            for (int bi = l; bi < 256; bi += 32) hw[bi] = 0u;
            __syncwarp();
            for (int i = l; i < LSEQ; i += 32) {
                const unsigned u = __float_as_uint(pr[i]);
                if ((u & pmask) == pref) atomicAdd(&hw[(u >> shift) & 255], 1u);
            }
            __syncwarp();
            // warp-parallel selection of the crossing bucket (from the top)
            const uint4 h0 = *(const uint4*)&hw[l * 8];
            const uint4 h1 = *(const uint4*)&hw[l * 8 + 4];
            const unsigned c8[8] = {h0.x, h0.y, h0.z, h0.w, h1.x, h1.y, h1.z, h1.w};
            int ssum = 0;
#pragma unroll
            for (int j = 0; j < 8; j++) ssum += (int)c8[j];
            int suf = ssum;                       // will become sum over lanes >= l
#pragma unroll
            for (int o = 1; o < 32; o <<= 1) {
                const int t = __shfl_down_sync(0xffffffffu, suf, o);
                if (l + o < 32) suf += t;
            }
            const int above = suf - ssum;         // sum over lanes > l
            const bool has = (above < need) && (suf >= need);
            const unsigned bal = __ballot_sync(0xffffffffu, has);
            const int src = __ffs(bal) - 1;       // exactly one lane qualifies
            int dsel = 0, cab = 0;
            if (has) {
                int cum = above;
#pragma unroll
                for (int j = 7; j >= 0; j--) {
                    if (cum + (int)c8[j] >= need) { dsel = l * 8 + j; cab = cum; break; }
                    cum += (int)c8[j];
                }
            }
            dsel = __shfl_sync(0xffffffffu, dsel, src);
            cab  = __shfl_sync(0xffffffffu, cab,  src);
            pref |= (unsigned)dsel << shift;
            need -= cab;
            __syncwarp();
        }
        const float thr = __uint_as_float(pref);
        for (int i = l; i < LSEQ; i += 32) {
            const float v = pr[i];
            pr[i] = (v >= thr) ? v * inv : 0.0f;
        }
    }
    __syncthreads();

    // ---- phase 3: ctx = P @ v, gate by q.  Thread s handles n in
    //      {2s, 2s+1, 2s+64, 2s+65, ...} so P loads are broadcast LDS.64. ----
    {
        const int g = tid & 15;          // dh slice g*4..+3
        const int s = tid >> 4;          // pair slot (0..31)
        const float* vb = g_v + (size_t)bh * LSEQ * NDH + g * 4;
        ull acc[16][2];
#pragma unroll
        for (int r = 0; r < 16; r++) { acc[r][0] = 0ull; acc[r][1] = 0ull; }

#define PROC3(V0, V1, N) do {                                               \
        const ull va01 = pk2((V0).x, (V0).y);                               \
        const ull va23 = pk2((V0).z, (V0).w);                               \
        const ull vb01 = pk2((V1).x, (V1).y);                               \
        const ull vb23 = pk2((V1).z, (V1).w);                               \
        _Pragma("unroll")                                                   \
        for (int r = 0; r < 16; r++) {                                      \
            const ull ppair = *(const ull*)&sP[r * PSTR + (N)];             \
            float p0, p1; upk2(ppair, p0, p1);                              \
            const ull pa = pk2(p0, p0);                                     \
            const ull pb = pk2(p1, p1);                                     \
            fma2(acc[r][0], pa, va01);                                      \
            fma2(acc[r][1], pa, va23);                                      \
            fma2(acc[r][0], pb, vb01);                                      \
            fma2(acc[r][1], pb, vb23);                                      \
        } } while (0)

        float4 v0 = *(const float4*)(vb + (size_t)(2 * s)     * NDH);
        float4 v1 = *(const float4*)(vb + (size_t)(2 * s + 1) * NDH);
        int n = 2 * s;
        for (; n + 64 < LSEQ; n += 64) {
            const float4 w0 = *(const float4*)(vb + (size_t)(n + 64) * NDH);
            const float4 w1 = *(const float4*)(vb + (size_t)(n + 65) * NDH);
            PROC3(v0, v1, n);
            v0 = w0; v1 = w1;
        }
        PROC3(v0, v1, n);
#undef PROC3
        __syncthreads();                  // all reads of sP done

        float* sR = sm;                   // overlay partials on sP: [32][16][64]
#pragma unroll
        for (int r = 0; r < 16; r++) {
            float a0, a1, a2, a3;
            upk2(acc[r][0], a0, a1);
            upk2(acc[r][1], a2, a3);
            *(float4*)&sR[((s * 16 + r) << 6) + (g << 2)] = make_float4(a0, a1, a2, a3);
        }
        __syncthreads();

        for (int o = tid; o < 1024; o += 512) {
            float c = 0.0f;
#pragma unroll
            for (int s2 = 0; s2 < 32; s2++) c += sR[(s2 << 10) + o];
            const int r = o >> 6, dh = o & 63;
            c *= sQT[dh * 16 + r];
            g_ctx[((size_t)(b * LSEQ) + m0 + r) * ND + h * NDH + dh] = c;
        }
    }
}

// ---------------------------------------------------------------------------
extern "C" void kernel_launch(void* const* d_in, const int* in_sizes, int n_in,
                              void* d_out, int out_size)
{
    const float* q_in = (const float*)d_in[0];
    const float* k_in = (const float*)d_in[1];
    const float* Wq   = (const float*)d_in[2];
    const float* bq   = (const float*)d_in[3];
    const float* Wk   = (const float*)d_in[4];
    const float* bk   = (const float*)d_in[5];
    const float* Wv   = (const float*)d_in[6];
    const float* bv   = (const float*)d_in[7];
    const float* Wo   = (const float*)d_in[8];
    const float* bo   = (const float*)d_in[9];
    const int*   mask = (const int*)d_in[10];
    float* out = (float*)d_out;

    void *pq = 0, *pk = 0, *pv = 0, *pctx = 0;
    cudaGetSymbolAddress(&pq, g_q);
    cudaGetSymbolAddress(&pk, g_kT);
    cudaGetSymbolAddress(&pv, g_v);
    cudaGetSymbolAddress(&pctx, g_ctx);

    const int smemb = (16 * PSTR + 1024 + 16 * 256) * 4;   // 151808 B
    cudaFuncSetAttribute(fused_attn, cudaFuncAttributeMaxDynamicSharedMemorySize, smemb);

    const dim3 thr(256);

    proj_qkv<<<dim3(ND / 128, (NB * LSEQ) / 128, 3), thr>>>(
        q_in, k_in, Wq, bq, Wk, bk, Wv, bv,
        (float*)pq, (float*)pk, (float*)pv);

    fused_attn<<<dim3(LSEQ / 16, NBH), 512, smemb>>>(mask);

    out_proj<<<dim3(ND / 128, (NB * LSEQ) / 128), thr>>>(
        (const float*)pctx, Wo, bo, out);
}